// round 15
// baseline (speedup 1.0000x reference)
#include <cuda_runtime.h>
#include <cuda_bf16.h>
#include <cstdint>

#define NMAX 50000
#define EMAX 640000
#define D    128
#define PK   72              // padded smem row stride (bf16)
#define TILE (128 * PK)      // 128x64 half-tile

// ---- scratch (device globals; no allocation allowed) ----
__device__ int   g_deg[NMAX];        // zeroed by k_assign for next replay
__device__ int   g_rowptr[NMAX];
__device__ int   g_rowend[NMAX];
__device__ int   g_cursor[NMAX];
__device__ int   g_col[EMAX];
__device__ float g_inv[NMAX];
__device__ int   g_total;

__device__ __align__(16) __nv_bfloat16 g_gh[(size_t)NMAX * D];   // agg split hi
__device__ __align__(16) __nv_bfloat16 g_gl[(size_t)NMAX * D];   // agg split lo
__device__ __align__(16) __nv_bfloat16 g_xh[(size_t)NMAX * D];   // x split hi
__device__ __align__(16) __nv_bfloat16 g_xl[(size_t)NMAX * D];
__device__ __align__(16) __nv_bfloat16 g_hh[(size_t)NMAX * D];   // h split hi
__device__ __align__(16) __nv_bfloat16 g_hl[(size_t)NMAX * D];
__device__ __align__(16) __nv_bfloat16 g_wh[4 * D * D];          // w1l,w1r,w2l,w2r hi
__device__ __align__(16) __nv_bfloat16 g_wl[4 * D * D];          // lo

// ============================ splits helper ============================
__device__ __forceinline__ void split2(float a, float b,
                                       __nv_bfloat162& hi, __nv_bfloat162& lo) {
    __nv_bfloat16 ha = __float2bfloat16_rn(a);
    __nv_bfloat16 hb = __float2bfloat16_rn(b);
    float la = a - __bfloat162float(ha);
    float lb = b - __bfloat162float(hb);
    hi = __halves2bfloat162(ha, hb);
    lo = __halves2bfloat162(__float2bfloat16_rn(la), __float2bfloat16_rn(lb));
}

// ============================ CSR build (scan-free) ============================
__global__ void k_deg(const int* __restrict__ dst, int E, int Nn) {
    int e = blockIdx.x * blockDim.x + threadIdx.x;
    if (e == 0) g_total = 0;
    if (e < E) {
        unsigned d = (unsigned)dst[e];
        if (d < (unsigned)Nn) atomicAdd(&g_deg[d], 1);
    }
}

__global__ void k_assign(int Nn) {
    int i = blockIdx.x * blockDim.x + threadIdx.x;
    if (i < Nn) {
        int d = g_deg[i];
        int start = atomicAdd(&g_total, d);
        g_rowptr[i] = start;
        g_cursor[i] = start;
        g_rowend[i] = start + d;
        g_inv[i]    = 1.0f / (float)(d > 0 ? d : 1);
        g_deg[i]    = 0;
    }
}

__global__ void k_fill_split(const int* __restrict__ src,
                             const int* __restrict__ dst, int E, int Nn,
                             const float* __restrict__ x,
                             const float* __restrict__ w0, const float* __restrict__ w1,
                             const float* __restrict__ w2, const float* __restrict__ w3,
                             int FB, int XB) {
    int bid = blockIdx.x;
    int tid = threadIdx.x;
    if (bid < FB) {
        int e = bid * 256 + tid;
        if (e < E) {
            unsigned d = (unsigned)dst[e];
            unsigned s = (unsigned)src[e];
            if (d < (unsigned)Nn && s < (unsigned)Nn) {
                int p = atomicAdd(&g_cursor[d], 1);
                g_col[p] = (int)s;
            }
        }
    } else if (bid < FB + XB) {
        int i = (bid - FB) * 256 + tid;
        int total4 = Nn * (D / 4);
        if (i < total4) {
            float4 v = *(const float4*)(x + (size_t)i * 4);
            __nv_bfloat162 h0, l0, h1, l1;
            split2(v.x, v.y, h0, l0);
            split2(v.z, v.w, h1, l1);
            *(__nv_bfloat162*)(g_xh + (size_t)i * 4)     = h0;
            *(__nv_bfloat162*)(g_xh + (size_t)i * 4 + 2) = h1;
            *(__nv_bfloat162*)(g_xl + (size_t)i * 4)     = l0;
            *(__nv_bfloat162*)(g_xl + (size_t)i * 4 + 2) = l1;
        }
    } else {
        int i = (bid - FB - XB) * 256 + tid;
        if (i < D * D) {
            const float* srcs[4] = {w0, w1, w2, w3};
#pragma unroll
            for (int m = 0; m < 4; m++) {
                float v = srcs[m][i];
                __nv_bfloat16 h = __float2bfloat16_rn(v);
                g_wh[m * D * D + i] = h;
                g_wl[m * D * D + i] = __float2bfloat16_rn(v - __bfloat162float(h));
            }
        }
    }
}

// ============== mean aggregation: one warp per node (L2-cap bound — frozen) ==========
template <bool IN_H>
__global__ void k_agg(const float* __restrict__ X, int Nn) {
    int node = (blockIdx.x * blockDim.x + threadIdx.x) >> 5;
    int lane = threadIdx.x & 31;
    if (node >= Nn) return;
    int r0 = g_rowptr[node];
    int r1 = g_rowend[node];
    float4 acc0 = make_float4(0.f, 0.f, 0.f, 0.f);
    float4 acc1 = make_float4(0.f, 0.f, 0.f, 0.f);

    auto loadv = [&](int s) -> float4 {
        if (IN_H) {
            size_t o = (size_t)s * D + lane * 4;
            __nv_bfloat162 h0 = *(const __nv_bfloat162*)(g_hh + o);
            __nv_bfloat162 h1 = *(const __nv_bfloat162*)(g_hh + o + 2);
            __nv_bfloat162 l0 = *(const __nv_bfloat162*)(g_hl + o);
            __nv_bfloat162 l1 = *(const __nv_bfloat162*)(g_hl + o + 2);
            return make_float4(__bfloat162float(h0.x) + __bfloat162float(l0.x),
                               __bfloat162float(h0.y) + __bfloat162float(l0.y),
                               __bfloat162float(h1.x) + __bfloat162float(l1.x),
                               __bfloat162float(h1.y) + __bfloat162float(l1.y));
        } else {
            return *(const float4*)(X + (size_t)s * D + lane * 4);
        }
    };

    int e = r0;
    for (; e + 1 < r1; e += 2) {
        int s0 = g_col[e];
        int s1 = g_col[e + 1];
        float4 v0 = loadv(s0);
        float4 v1 = loadv(s1);
        acc0.x += v0.x; acc0.y += v0.y; acc0.z += v0.z; acc0.w += v0.w;
        acc1.x += v1.x; acc1.y += v1.y; acc1.z += v1.z; acc1.w += v1.w;
    }
    if (e < r1) {
        float4 v0 = loadv(g_col[e]);
        acc0.x += v0.x; acc0.y += v0.y; acc0.z += v0.z; acc0.w += v0.w;
    }
    float inv = g_inv[node];
    float a = (acc0.x + acc1.x) * inv;
    float b = (acc0.y + acc1.y) * inv;
    float c = (acc0.z + acc1.z) * inv;
    float d = (acc0.w + acc1.w) * inv;
    __nv_bfloat162 h0, l0, h1, l1;
    split2(a, b, h0, l0);
    split2(c, d, h1, l1);
    size_t base = (size_t)node * D + lane * 4;
    *(__nv_bfloat162*)(g_gh + base)     = h0;
    *(__nv_bfloat162*)(g_gh + base + 2) = h1;
    *(__nv_bfloat162*)(g_gl + base)     = l0;
    *(__nv_bfloat162*)(g_gl + base + 2) = l1;
}

// ===== tensor-core fused dual GEMM (split-bf16, BK=64, LDSM, 3 CTAs/SM) ======
__device__ __forceinline__ void mma16816(float c[4], uint32_t a0, uint32_t a1,
                                         uint32_t a2, uint32_t a3,
                                         uint32_t b0, uint32_t b1) {
    asm volatile(
        "mma.sync.aligned.m16n8k16.row.col.f32.bf16.bf16.f32 "
        "{%0,%1,%2,%3}, {%4,%5,%6,%7}, {%8,%9}, {%0,%1,%2,%3};\n"
        : "+f"(c[0]), "+f"(c[1]), "+f"(c[2]), "+f"(c[3])
        : "r"(a0), "r"(a1), "r"(a2), "r"(a3), "r"(b0), "r"(b1));
}

__device__ __forceinline__ void ldsm4(uint32_t& r0, uint32_t& r1,
                                      uint32_t& r2, uint32_t& r3, uint32_t addr) {
    asm volatile("ldmatrix.sync.aligned.m8n8.x4.shared.b16 {%0,%1,%2,%3}, [%4];\n"
                 : "=r"(r0), "=r"(r1), "=r"(r2), "=r"(r3) : "r"(addr));
}

__device__ __forceinline__ void cp16(uint32_t saddr, const void* gaddr, int srcBytes) {
    asm volatile("cp.async.cg.shared.global [%0], [%1], 16, %2;\n"
                 :: "r"(saddr), "l"(gaddr), "r"(srcBytes));
}

template <int LAYER>   // 1: relu, writes g_hh/g_hl ; 2: writes outp fp32
__global__ void __launch_bounds__(256, 3)
k_mma(const float* __restrict__ bias, float* __restrict__ outp, int Nn)
{
    extern __shared__ __nv_bfloat16 smem[];
    // double-buffered 128x64 tiles: As[2], Bs[2]  (73.7 KB -> 3 CTAs/SM, 1 wave)
    __nv_bfloat16* As[2] = {smem,            smem + TILE};
    __nv_bfloat16* Bs[2] = {smem + 2 * TILE, smem + 3 * TILE};

    const __nv_bfloat16* A2h = (LAYER == 1) ? g_xh : g_hh;
    const __nv_bfloat16* A2l = (LAYER == 1) ? g_xl : g_hl;
    const int wl = (LAYER == 1) ? 0 : 2;
    const int wr = (LAYER == 1) ? 1 : 3;
    const __nv_bfloat16* Wlh = g_wh + wl * D * D;
    const __nv_bfloat16* Wll = g_wl + wl * D * D;
    const __nv_bfloat16* Wrh = g_wh + wr * D * D;
    const __nv_bfloat16* Wrl = g_wl + wr * D * D;

    // 6 virtual-K slabs of 128: Ah@Wh, Al@Wh, Ah@Wl per segment
    const __nv_bfloat16* Aslab[6] = {g_gh, g_gl, g_gh, A2h, A2l, A2h};
    const __nv_bfloat16* Wslab[6] = {Wlh,  Wlh,  Wll,  Wrh,  Wrh,  Wrl};

    int tid = threadIdx.x;
    int m0  = blockIdx.x * 128;
    int warp = tid >> 5, lane = tid & 31;
    int wm = (warp >> 2) * 64;      // 2 warps in m
    int wn = (warp & 3) * 32;       // 4 warps in n
    int g  = lane >> 2, ctg = lane & 3;

    // ldmatrix lane addressing
    int lr = lane & 7, lq = lane >> 3;
    int aRow = (lq & 1) * 8 + lr;      // + wm + mi*16
    int aKof = (lq >> 1) * 8;          // + p*16
    int bRow = (lq >> 1) * 8 + lr;     // + wn + pair*16
    int bKof = (lq & 1) * 8;           // + p*16

    uint32_t AsAddr[2], BsAddr[2];
#pragma unroll
    for (int i = 0; i < 2; i++) {
        AsAddr[i] = (uint32_t)__cvta_generic_to_shared(As[i]);
        BsAddr[i] = (uint32_t)__cvta_generic_to_shared(Bs[i]);
    }

    float acc[4][4][4] = {};

    // stage s -> buffer s & 1 ; one 128x64 tile each for A and W
    auto ldgsts = [&](int s) {
        int buf  = s & 1;
        int slab = s >> 1, koff = (s & 1) * 64;
        const __nv_bfloat16* Ap = Aslab[slab];
        const __nv_bfloat16* Wp = Wslab[slab];
#pragma unroll
        for (int l = 0; l < 4; l++) {
            int u = tid + l * 256;          // 0..1023 uint4 slots
            int row = u >> 3, kq = u & 7;   // 128 rows x 8 chunks
            int gm = m0 + row;
            int gmc = gm < Nn ? gm : 0;
            int sb  = gm < Nn ? 16 : 0;
            uint32_t sa = AsAddr[buf] + (uint32_t)(row * PK + kq * 8) * 2;
            cp16(sa, Ap + (size_t)gmc * D + koff + kq * 8, sb);
            uint32_t sw = BsAddr[buf] + (uint32_t)(row * PK + kq * 8) * 2;
            cp16(sw, Wp + row * D + koff + kq * 8, 16);
        }
        asm volatile("cp.async.commit_group;\n" ::: "memory");
    };

    auto compute = [&](int s) {
        int buf = s & 1;
        uint32_t Ab = AsAddr[buf];
        uint32_t Wb = BsAddr[buf];
#pragma unroll
        for (int p = 0; p < 4; p++) {       // four k16 phases per BK=64
            uint32_t bfr[4][2];
            {
                uint32_t baseB = Wb + (uint32_t)((wn + bRow) * PK + p * 16 + bKof) * 2;
                ldsm4(bfr[0][0], bfr[0][1], bfr[1][0], bfr[1][1], baseB);
                ldsm4(bfr[2][0], bfr[2][1], bfr[3][0], bfr[3][1],
                      baseB + (uint32_t)(16 * PK) * 2);
            }
#pragma unroll
            for (int mi = 0; mi < 4; mi++) {
                uint32_t a0, a1, a2, a3;
                uint32_t baseA = Ab + (uint32_t)((wm + mi * 16 + aRow) * PK + p * 16 + aKof) * 2;
                ldsm4(a0, a1, a2, a3, baseA);
#pragma unroll
                for (int ni = 0; ni < 4; ni++)
                    mma16816(acc[mi][ni], a0, a1, a2, a3, bfr[ni][0], bfr[ni][1]);
            }
        }
    };

    // double-buffer pipeline: load s+1 during compute(s)
    ldgsts(0);
    asm volatile("cp.async.wait_group 0;\n" ::: "memory");
    __syncthreads();
#pragma unroll
    for (int s = 0; s < 12; s++) {
        if (s < 11) ldgsts(s + 1);
        compute(s);
        if (s < 11) asm volatile("cp.async.wait_group 0;\n" ::: "memory");
        __syncthreads();
    }

    // epilogue
#pragma unroll
    for (int mi = 0; mi < 4; mi++) {
        int r0 = m0 + wm + mi * 16 + g;
        int r1 = r0 + 8;
#pragma unroll
        for (int ni = 0; ni < 4; ni++) {
            int col = wn + ni * 8 + ctg * 2;
            float2 b2 = *(const float2*)(bias + col);
            float v00 = acc[mi][ni][0] + b2.x, v01 = acc[mi][ni][1] + b2.y;
            float v10 = acc[mi][ni][2] + b2.x, v11 = acc[mi][ni][3] + b2.y;
            if (LAYER == 1) {
                v00 = fmaxf(v00, 0.f); v01 = fmaxf(v01, 0.f);
                v10 = fmaxf(v10, 0.f); v11 = fmaxf(v11, 0.f);
                if (r0 < Nn) {
                    size_t o = (size_t)r0 * D + col;
                    __nv_bfloat162 h2, l2; split2(v00, v01, h2, l2);
                    *(__nv_bfloat162*)(g_hh + o) = h2;
                    *(__nv_bfloat162*)(g_hl + o) = l2;
                }
                if (r1 < Nn) {
                    size_t o = (size_t)r1 * D + col;
                    __nv_bfloat162 h2, l2; split2(v10, v11, h2, l2);
                    *(__nv_bfloat162*)(g_hh + o) = h2;
                    *(__nv_bfloat162*)(g_hl + o) = l2;
                }
            } else {
                if (r0 < Nn) *(float2*)(outp + (size_t)r0 * D + col) = make_float2(v00, v01);
                if (r1 < Nn) *(float2*)(outp + (size_t)r1 * D + col) = make_float2(v10, v11);
            }
        }
    }
}

// ============================ launch ============================
extern "C" void kernel_launch(void* const* d_in, const int* in_sizes, int n_in,
                              void* d_out, int out_size)
{
    const float* x   = (const float*)d_in[0];
    const int*   ei  = (const int*)d_in[1];       // int32 (JAX x64 disabled)
    const float* w1l = (const float*)d_in[2];
    const float* b1  = (const float*)d_in[3];
    const float* w1r = (const float*)d_in[4];
    const float* w2l = (const float*)d_in[5];
    const float* b2  = (const float*)d_in[6];
    const float* w2r = (const float*)d_in[7];
    float*       out = (float*)d_out;

    int Nn = in_sizes[0] / D;
    int E  = in_sizes[1] / 2;
    const int* src = ei;
    const int* dst = ei + E;

    int FB = (E + 255) / 256;
    int XB = (Nn * (D / 4) + 255) / 256;
    int WB = (D * D + 255) / 256;

    const int SMEM = 4 * TILE * (int)sizeof(__nv_bfloat16);   // 73728 B
    static bool attrDone = false;   // idempotent host-side config (pre-capture)
    if (!attrDone) {
        cudaFuncSetAttribute(k_mma<1>, cudaFuncAttributeMaxDynamicSharedMemorySize, SMEM);
        cudaFuncSetAttribute(k_mma<2>, cudaFuncAttributeMaxDynamicSharedMemorySize, SMEM);
        attrDone = true;
    }

    k_deg<<<FB, 256>>>(dst, E, Nn);
    k_assign<<<(Nn + 255) / 256, 256>>>(Nn);
    k_fill_split<<<FB + XB + WB, 256>>>(src, dst, E, Nn, x, w1l, w1r, w2l, w2r, FB, XB);

    int aggBlocks  = (Nn * 32 + 255) / 256;
    int gemmBlocks = (Nn + 127) / 128;

    k_agg<false><<<aggBlocks, 256>>>(x, Nn);
    k_mma<1><<<gemmBlocks, 256, SMEM>>>(b1, nullptr, Nn);

    k_agg<true><<<aggBlocks, 256>>>(nullptr, Nn);
    k_mma<2><<<gemmBlocks, 256, SMEM>>>(b2, out, Nn);
}

// round 16
// speedup vs baseline: 1.7119x; 1.7119x over previous
#include <cuda_runtime.h>
#include <cuda_bf16.h>
#include <cstdint>

#define NMAX 50000
#define EMAX 640000
#define D    128
#define PK   72              // padded smem row stride (bf16)
#define TILE (128 * PK)      // 128x64 half-tile

// ---- scratch (device globals; no allocation allowed) ----
__device__ int   g_deg[NMAX];        // zeroed by k_assign for next replay
__device__ int   g_rowptr[NMAX];
__device__ int   g_rowend[NMAX];
__device__ int   g_cursor[NMAX];
__device__ int   g_col[EMAX];
__device__ float g_inv[NMAX];
__device__ int   g_total;

__device__ __align__(16) __nv_bfloat16 g_gh[(size_t)NMAX * D];   // agg split hi
__device__ __align__(16) __nv_bfloat16 g_gl[(size_t)NMAX * D];   // agg split lo
__device__ __align__(16) __nv_bfloat16 g_xh[(size_t)NMAX * D];   // x split hi
__device__ __align__(16) __nv_bfloat16 g_xl[(size_t)NMAX * D];
__device__ __align__(16) __nv_bfloat16 g_hh[(size_t)NMAX * D];   // h split hi
__device__ __align__(16) __nv_bfloat16 g_hl[(size_t)NMAX * D];
__device__ __align__(16) __nv_bfloat16 g_wh[4 * D * D];          // w1l,w1r,w2l,w2r hi
__device__ __align__(16) __nv_bfloat16 g_wl[4 * D * D];          // lo

// ============================ splits helper ============================
__device__ __forceinline__ void split2(float a, float b,
                                       __nv_bfloat162& hi, __nv_bfloat162& lo) {
    __nv_bfloat16 ha = __float2bfloat16_rn(a);
    __nv_bfloat16 hb = __float2bfloat16_rn(b);
    float la = a - __bfloat162float(ha);
    float lb = b - __bfloat162float(hb);
    hi = __halves2bfloat162(ha, hb);
    lo = __halves2bfloat162(__float2bfloat16_rn(la), __float2bfloat16_rn(lb));
}

// ============================ CSR build (scan-free) ============================
// 4 edges per thread via int4: 4 independent atomics in flight (MLP=4).
__global__ void k_deg(const int* __restrict__ dst, int E, int Nn) {
    int t = blockIdx.x * blockDim.x + threadIdx.x;
    if (t == 0) g_total = 0;
    int base = t * 4;
    if (base + 3 < E) {
        int4 d4 = *(const int4*)(dst + base);
        if ((unsigned)d4.x < (unsigned)Nn) atomicAdd(&g_deg[d4.x], 1);
        if ((unsigned)d4.y < (unsigned)Nn) atomicAdd(&g_deg[d4.y], 1);
        if ((unsigned)d4.z < (unsigned)Nn) atomicAdd(&g_deg[d4.z], 1);
        if ((unsigned)d4.w < (unsigned)Nn) atomicAdd(&g_deg[d4.w], 1);
    } else {
        for (int e = base; e < E; e++) {
            unsigned d = (unsigned)dst[e];
            if (d < (unsigned)Nn) atomicAdd(&g_deg[d], 1);
        }
    }
}

__global__ void k_assign(int Nn) {
    int i = blockIdx.x * blockDim.x + threadIdx.x;
    if (i < Nn) {
        int d = g_deg[i];
        int start = atomicAdd(&g_total, d);
        g_rowptr[i] = start;
        g_cursor[i] = start;
        g_rowend[i] = start + d;
        g_inv[i]    = 1.0f / (float)(d > 0 ? d : 1);
        g_deg[i]    = 0;
    }
}

__global__ void k_fill_split(const int* __restrict__ src,
                             const int* __restrict__ dst, int E, int Nn,
                             const float* __restrict__ x,
                             const float* __restrict__ w0, const float* __restrict__ w1,
                             const float* __restrict__ w2, const float* __restrict__ w3,
                             int FB, int XB) {
    int bid = blockIdx.x;
    int tid = threadIdx.x;
    if (bid < FB) {
        // 4 edges per thread: int4 loads of src/dst, 4 independent ticket atomics
        int t = bid * 256 + tid;
        int base = t * 4;
        if (base + 3 < E) {
            int4 d4 = *(const int4*)(dst + base);
            int4 s4 = *(const int4*)(src + base);
            if ((unsigned)d4.x < (unsigned)Nn && (unsigned)s4.x < (unsigned)Nn)
                g_col[atomicAdd(&g_cursor[d4.x], 1)] = s4.x;
            if ((unsigned)d4.y < (unsigned)Nn && (unsigned)s4.y < (unsigned)Nn)
                g_col[atomicAdd(&g_cursor[d4.y], 1)] = s4.y;
            if ((unsigned)d4.z < (unsigned)Nn && (unsigned)s4.z < (unsigned)Nn)
                g_col[atomicAdd(&g_cursor[d4.z], 1)] = s4.z;
            if ((unsigned)d4.w < (unsigned)Nn && (unsigned)s4.w < (unsigned)Nn)
                g_col[atomicAdd(&g_cursor[d4.w], 1)] = s4.w;
        } else {
            for (int e = base; e < E; e++) {
                unsigned d = (unsigned)dst[e];
                unsigned s = (unsigned)src[e];
                if (d < (unsigned)Nn && s < (unsigned)Nn)
                    g_col[atomicAdd(&g_cursor[d], 1)] = (int)s;
            }
        }
    } else if (bid < FB + XB) {
        int i = (bid - FB) * 256 + tid;
        int total4 = Nn * (D / 4);
        if (i < total4) {
            float4 v = *(const float4*)(x + (size_t)i * 4);
            __nv_bfloat162 h0, l0, h1, l1;
            split2(v.x, v.y, h0, l0);
            split2(v.z, v.w, h1, l1);
            *(__nv_bfloat162*)(g_xh + (size_t)i * 4)     = h0;
            *(__nv_bfloat162*)(g_xh + (size_t)i * 4 + 2) = h1;
            *(__nv_bfloat162*)(g_xl + (size_t)i * 4)     = l0;
            *(__nv_bfloat162*)(g_xl + (size_t)i * 4 + 2) = l1;
        }
    } else {
        int i = (bid - FB - XB) * 256 + tid;
        if (i < D * D) {
            const float* srcs[4] = {w0, w1, w2, w3};
#pragma unroll
            for (int m = 0; m < 4; m++) {
                float v = srcs[m][i];
                __nv_bfloat16 h = __float2bfloat16_rn(v);
                g_wh[m * D * D + i] = h;
                g_wl[m * D * D + i] = __float2bfloat16_rn(v - __bfloat162float(h));
            }
        }
    }
}

// ============== mean aggregation: one warp per node (L2-cap bound — frozen) ==========
template <bool IN_H>
__global__ void k_agg(const float* __restrict__ X, int Nn) {
    int node = (blockIdx.x * blockDim.x + threadIdx.x) >> 5;
    int lane = threadIdx.x & 31;
    if (node >= Nn) return;
    int r0 = g_rowptr[node];
    int r1 = g_rowend[node];
    float4 acc0 = make_float4(0.f, 0.f, 0.f, 0.f);
    float4 acc1 = make_float4(0.f, 0.f, 0.f, 0.f);

    auto loadv = [&](int s) -> float4 {
        if (IN_H) {
            size_t o = (size_t)s * D + lane * 4;
            __nv_bfloat162 h0 = *(const __nv_bfloat162*)(g_hh + o);
            __nv_bfloat162 h1 = *(const __nv_bfloat162*)(g_hh + o + 2);
            __nv_bfloat162 l0 = *(const __nv_bfloat162*)(g_hl + o);
            __nv_bfloat162 l1 = *(const __nv_bfloat162*)(g_hl + o + 2);
            return make_float4(__bfloat162float(h0.x) + __bfloat162float(l0.x),
                               __bfloat162float(h0.y) + __bfloat162float(l0.y),
                               __bfloat162float(h1.x) + __bfloat162float(l1.x),
                               __bfloat162float(h1.y) + __bfloat162float(l1.y));
        } else {
            return *(const float4*)(X + (size_t)s * D + lane * 4);
        }
    };

    int e = r0;
    for (; e + 1 < r1; e += 2) {
        int s0 = g_col[e];
        int s1 = g_col[e + 1];
        float4 v0 = loadv(s0);
        float4 v1 = loadv(s1);
        acc0.x += v0.x; acc0.y += v0.y; acc0.z += v0.z; acc0.w += v0.w;
        acc1.x += v1.x; acc1.y += v1.y; acc1.z += v1.z; acc1.w += v1.w;
    }
    if (e < r1) {
        float4 v0 = loadv(g_col[e]);
        acc0.x += v0.x; acc0.y += v0.y; acc0.z += v0.z; acc0.w += v0.w;
    }
    float inv = g_inv[node];
    float a = (acc0.x + acc1.x) * inv;
    float b = (acc0.y + acc1.y) * inv;
    float c = (acc0.z + acc1.z) * inv;
    float d = (acc0.w + acc1.w) * inv;
    __nv_bfloat162 h0, l0, h1, l1;
    split2(a, b, h0, l0);
    split2(c, d, h1, l1);
    size_t base = (size_t)node * D + lane * 4;
    *(__nv_bfloat162*)(g_gh + base)     = h0;
    *(__nv_bfloat162*)(g_gh + base + 2) = h1;
    *(__nv_bfloat162*)(g_gl + base)     = l0;
    *(__nv_bfloat162*)(g_gl + base + 2) = l1;
}

// ===== tensor-core fused dual GEMM (split-bf16, BK=64, cp.async triple, LDSM) ======
// (R14 configuration — 2 CTAs/SM; 3 CTAs/SM spills, measured +109us in R15)
__device__ __forceinline__ void mma16816(float c[4], uint32_t a0, uint32_t a1,
                                         uint32_t a2, uint32_t a3,
                                         uint32_t b0, uint32_t b1) {
    asm volatile(
        "mma.sync.aligned.m16n8k16.row.col.f32.bf16.bf16.f32 "
        "{%0,%1,%2,%3}, {%4,%5,%6,%7}, {%8,%9}, {%0,%1,%2,%3};\n"
        : "+f"(c[0]), "+f"(c[1]), "+f"(c[2]), "+f"(c[3])
        : "r"(a0), "r"(a1), "r"(a2), "r"(a3), "r"(b0), "r"(b1));
}

__device__ __forceinline__ void ldsm4(uint32_t& r0, uint32_t& r1,
                                      uint32_t& r2, uint32_t& r3, uint32_t addr) {
    asm volatile("ldmatrix.sync.aligned.m8n8.x4.shared.b16 {%0,%1,%2,%3}, [%4];\n"
                 : "=r"(r0), "=r"(r1), "=r"(r2), "=r"(r3) : "r"(addr));
}

__device__ __forceinline__ void cp16(uint32_t saddr, const void* gaddr, int srcBytes) {
    asm volatile("cp.async.cg.shared.global [%0], [%1], 16, %2;\n"
                 :: "r"(saddr), "l"(gaddr), "r"(srcBytes));
}

template <int LAYER>   // 1: relu, writes g_hh/g_hl ; 2: writes outp fp32
__global__ void __launch_bounds__(256, 2)
k_mma(const float* __restrict__ bias, float* __restrict__ outp, int Nn)
{
    extern __shared__ __nv_bfloat16 smem[];
    // triple-buffered 128x64 tiles: As[3], Bs[3]
    __nv_bfloat16* As[3] = {smem,            smem + TILE,     smem + 2 * TILE};
    __nv_bfloat16* Bs[3] = {smem + 3 * TILE, smem + 4 * TILE, smem + 5 * TILE};

    const __nv_bfloat16* A2h = (LAYER == 1) ? g_xh : g_hh;
    const __nv_bfloat16* A2l = (LAYER == 1) ? g_xl : g_hl;
    const int wl = (LAYER == 1) ? 0 : 2;
    const int wr = (LAYER == 1) ? 1 : 3;
    const __nv_bfloat16* Wlh = g_wh + wl * D * D;
    const __nv_bfloat16* Wll = g_wl + wl * D * D;
    const __nv_bfloat16* Wrh = g_wh + wr * D * D;
    const __nv_bfloat16* Wrl = g_wl + wr * D * D;

    // 6 virtual-K slabs of 128: Ah@Wh, Al@Wh, Ah@Wl per segment
    const __nv_bfloat16* Aslab[6] = {g_gh, g_gl, g_gh, A2h, A2l, A2h};
    const __nv_bfloat16* Wslab[6] = {Wlh,  Wlh,  Wll,  Wrh,  Wrh,  Wrl};

    int tid = threadIdx.x;
    int m0  = blockIdx.x * 128;
    int warp = tid >> 5, lane = tid & 31;
    int wm = (warp >> 2) * 64;      // 2 warps in m
    int wn = (warp & 3) * 32;       // 4 warps in n
    int g  = lane >> 2, ctg = lane & 3;

    // ldmatrix lane addressing
    int lr = lane & 7, lq = lane >> 3;
    int aRow = (lq & 1) * 8 + lr;      // + wm + mi*16
    int aKof = (lq >> 1) * 8;          // + p*16
    int bRow = (lq >> 1) * 8 + lr;     // + wn + pair*16
    int bKof = (lq & 1) * 8;           // + p*16

    uint32_t AsAddr[3], BsAddr[3];
#pragma unroll
    for (int i = 0; i < 3; i++) {
        AsAddr[i] = (uint32_t)__cvta_generic_to_shared(As[i]);
        BsAddr[i] = (uint32_t)__cvta_generic_to_shared(Bs[i]);
    }

    float acc[4][4][4] = {};

    // stage s -> buffer s % 3 ; one 128x64 tile each for A and W
    auto ldgsts = [&](int s) {
        int buf  = s % 3;
        int slab = s >> 1, koff = (s & 1) * 64;
        const __nv_bfloat16* Ap = Aslab[slab];
        const __nv_bfloat16* Wp = Wslab[slab];
#pragma unroll
        for (int l = 0; l < 4; l++) {
            int u = tid + l * 256;          // 0..1023 uint4 slots
            int row = u >> 3, kq = u & 7;   // 128 rows x 8 chunks
            int gm = m0 + row;
            int gmc = gm < Nn ? gm : 0;
            int sb  = gm < Nn ? 16 : 0;
            uint32_t sa = AsAddr[buf] + (uint32_t)(row * PK + kq * 8) * 2;
            cp16(sa, Ap + (size_t)gmc * D + koff + kq * 8, sb);
            uint32_t sw = BsAddr[buf] + (uint32_t)(row * PK + kq * 8) * 2;
            cp16(sw, Wp + row * D + koff + kq * 8, 16);
        }
        asm volatile("cp.async.commit_group;\n" ::: "memory");
    };

    auto compute = [&](int s) {
        int buf = s % 3;
        uint32_t Ab = AsAddr[buf];
        uint32_t Wb = BsAddr[buf];
#pragma unroll
        for (int p = 0; p < 4; p++) {       // four k16 phases per BK=64
            uint32_t bfr[4][2];
            {
                uint32_t baseB = Wb + (uint32_t)((wn + bRow) * PK + p * 16 + bKof) * 2;
                ldsm4(bfr[0][0], bfr[0][1], bfr[1][0], bfr[1][1], baseB);
                ldsm4(bfr[2][0], bfr[2][1], bfr[3][0], bfr[3][1],
                      baseB + (uint32_t)(16 * PK) * 2);
            }
#pragma unroll
            for (int mi = 0; mi < 4; mi++) {
                uint32_t a0, a1, a2, a3;
                uint32_t baseA = Ab + (uint32_t)((wm + mi * 16 + aRow) * PK + p * 16 + aKof) * 2;
                ldsm4(a0, a1, a2, a3, baseA);
#pragma unroll
                for (int ni = 0; ni < 4; ni++)
                    mma16816(acc[mi][ni], a0, a1, a2, a3, bfr[ni][0], bfr[ni][1]);
            }
        }
    };

    // pipeline: 2 stages in flight; wait leaves the newest group pending
    ldgsts(0);
    ldgsts(1);
#pragma unroll
    for (int s = 0; s < 12; s++) {
        if (s < 11) {
            asm volatile("cp.async.wait_group 1;\n" ::: "memory");  // group s done
        } else {
            asm volatile("cp.async.wait_group 0;\n" ::: "memory");
        }
        __syncthreads();
        if (s < 10) ldgsts(s + 2);          // buffer (s+2)%3 free: compute(s-1) done
        compute(s);
    }

    // epilogue
#pragma unroll
    for (int mi = 0; mi < 4; mi++) {
        int r0 = m0 + wm + mi * 16 + g;
        int r1 = r0 + 8;
#pragma unroll
        for (int ni = 0; ni < 4; ni++) {
            int col = wn + ni * 8 + ctg * 2;
            float2 b2 = *(const float2*)(bias + col);
            float v00 = acc[mi][ni][0] + b2.x, v01 = acc[mi][ni][1] + b2.y;
            float v10 = acc[mi][ni][2] + b2.x, v11 = acc[mi][ni][3] + b2.y;
            if (LAYER == 1) {
                v00 = fmaxf(v00, 0.f); v01 = fmaxf(v01, 0.f);
                v10 = fmaxf(v10, 0.f); v11 = fmaxf(v11, 0.f);
                if (r0 < Nn) {
                    size_t o = (size_t)r0 * D + col;
                    __nv_bfloat162 h2, l2; split2(v00, v01, h2, l2);
                    *(__nv_bfloat162*)(g_hh + o) = h2;
                    *(__nv_bfloat162*)(g_hl + o) = l2;
                }
                if (r1 < Nn) {
                    size_t o = (size_t)r1 * D + col;
                    __nv_bfloat162 h2, l2; split2(v10, v11, h2, l2);
                    *(__nv_bfloat162*)(g_hh + o) = h2;
                    *(__nv_bfloat162*)(g_hl + o) = l2;
                }
            } else {
                if (r0 < Nn) *(float2*)(outp + (size_t)r0 * D + col) = make_float2(v00, v01);
                if (r1 < Nn) *(float2*)(outp + (size_t)r1 * D + col) = make_float2(v10, v11);
            }
        }
    }
}

// ============================ launch ============================
extern "C" void kernel_launch(void* const* d_in, const int* in_sizes, int n_in,
                              void* d_out, int out_size)
{
    const float* x   = (const float*)d_in[0];
    const int*   ei  = (const int*)d_in[1];       // int32 (JAX x64 disabled)
    const float* w1l = (const float*)d_in[2];
    const float* b1  = (const float*)d_in[3];
    const float* w1r = (const float*)d_in[4];
    const float* w2l = (const float*)d_in[5];
    const float* b2  = (const float*)d_in[6];
    const float* w2r = (const float*)d_in[7];
    float*       out = (float*)d_out;

    int Nn = in_sizes[0] / D;
    int E  = in_sizes[1] / 2;
    const int* src = ei;
    const int* dst = ei + E;

    int E4 = (E + 3) / 4;                        // 4 edges per thread
    int FB = (E4 + 255) / 256;
    int XB = (Nn * (D / 4) + 255) / 256;
    int WB = (D * D + 255) / 256;

    const int SMEM = 6 * TILE * (int)sizeof(__nv_bfloat16);   // 110592 B
    static bool attrDone = false;   // idempotent host-side config (pre-capture)
    if (!attrDone) {
        cudaFuncSetAttribute(k_mma<1>, cudaFuncAttributeMaxDynamicSharedMemorySize, SMEM);
        cudaFuncSetAttribute(k_mma<2>, cudaFuncAttributeMaxDynamicSharedMemorySize, SMEM);
        attrDone = true;
    }

    k_deg<<<FB, 256>>>(dst, E, Nn);
    k_assign<<<(Nn + 255) / 256, 256>>>(Nn);
    k_fill_split<<<FB + XB + WB, 256>>>(src, dst, E, Nn, x, w1l, w1r, w2l, w2r, FB, XB);

    int aggBlocks  = (Nn * 32 + 255) / 256;
    int gemmBlocks = (Nn + 127) / 128;

    k_agg<false><<<aggBlocks, 256>>>(x, Nn);
    k_mma<1><<<gemmBlocks, 256, SMEM>>>(b1, nullptr, Nn);

    k_agg<true><<<aggBlocks, 256>>>(nullptr, Nn);
    k_mma<2><<<gemmBlocks, 256, SMEM>>>(b2, out, Nn);
}